// round 5
// baseline (speedup 1.0000x reference)
#include <cuda_runtime.h>
#include <math.h>

#define NROWS (8 * 2048)   // 16384 total rows (B*S)
#define EDIM  512
#define HEADS 8
#define HDIM  64
#define SEQ   2048
#define BATCH 8

// Scratch (device globals: allocation-free per harness rules)
__device__ __align__(16) float g_q[NROWS * EDIM];
__device__ __align__(16) float g_k[NROWS * EDIM];
__device__ __align__(16) float g_v[NROWS * EDIM];
__device__ __align__(16) float g_ao[NROWS * EDIM];

// ---------------------------------------------------------------------------
// GEMM: C[N,512] = A[N,512] @ W[512,512] + bias   (128x128x8, 8x8/thread)
// ---------------------------------------------------------------------------
__global__ void __launch_bounds__(256, 2) gemm_bias_kernel(
    const float* __restrict__ A, const float* __restrict__ W,
    const float* __restrict__ bias, float* __restrict__ C)
{
    __shared__ __align__(16) float As[8][132];  // stored transposed: As[k][m]
    __shared__ __align__(16) float Bs[8][128];  // Bs[k][n]

    const int tid = threadIdx.x;
    const int tx = tid & 15;          // 0..15 (n direction)
    const int ty = tid >> 4;          // 0..15 (m direction)
    const int rowBlock = blockIdx.y * 128;
    const int colBlock = blockIdx.x * 128;

    const int aRow = tid >> 1;        // 0..127
    const int aCol = (tid & 1) * 4;   // 0 or 4
    const int bRow = tid >> 5;        // 0..7
    const int bCol = (tid & 31) * 4;  // 0..124

    float acc[8][8];
    #pragma unroll
    for (int i = 0; i < 8; i++)
        #pragma unroll
        for (int j = 0; j < 8; j++) acc[i][j] = 0.f;

    for (int k0 = 0; k0 < 512; k0 += 8) {
        float4 av = *reinterpret_cast<const float4*>(
            A + (size_t)(rowBlock + aRow) * 512 + k0 + aCol);
        As[aCol + 0][aRow] = av.x;
        As[aCol + 1][aRow] = av.y;
        As[aCol + 2][aRow] = av.z;
        As[aCol + 3][aRow] = av.w;
        *reinterpret_cast<float4*>(&Bs[bRow][bCol]) =
            *reinterpret_cast<const float4*>(
                W + (size_t)(k0 + bRow) * 512 + colBlock + bCol);
        __syncthreads();

        #pragma unroll
        for (int kk = 0; kk < 8; kk++) {
            float4 a0 = *reinterpret_cast<const float4*>(&As[kk][ty * 4]);
            float4 a1 = *reinterpret_cast<const float4*>(&As[kk][64 + ty * 4]);
            float4 b0 = *reinterpret_cast<const float4*>(&Bs[kk][tx * 4]);
            float4 b1 = *reinterpret_cast<const float4*>(&Bs[kk][64 + tx * 4]);
            float ar[8] = {a0.x, a0.y, a0.z, a0.w, a1.x, a1.y, a1.z, a1.w};
            float br[8] = {b0.x, b0.y, b0.z, b0.w, b1.x, b1.y, b1.z, b1.w};
            #pragma unroll
            for (int i = 0; i < 8; i++)
                #pragma unroll
                for (int j = 0; j < 8; j++)
                    acc[i][j] = fmaf(ar[i], br[j], acc[i][j]);
        }
        __syncthreads();
    }

    float4 bias0 = *reinterpret_cast<const float4*>(bias + colBlock + tx * 4);
    float4 bias1 = *reinterpret_cast<const float4*>(bias + colBlock + 64 + tx * 4);
    #pragma unroll
    for (int i = 0; i < 8; i++) {
        int m = rowBlock + ((i < 4) ? (ty * 4 + i) : (64 + ty * 4 + (i - 4)));
        float4 c0 = make_float4(acc[i][0] + bias0.x, acc[i][1] + bias0.y,
                                acc[i][2] + bias0.z, acc[i][3] + bias0.w);
        float4 c1 = make_float4(acc[i][4] + bias1.x, acc[i][5] + bias1.y,
                                acc[i][6] + bias1.z, acc[i][7] + bias1.w);
        *reinterpret_cast<float4*>(C + (size_t)m * 512 + colBlock + tx * 4) = c0;
        *reinterpret_cast<float4*>(C + (size_t)m * 512 + colBlock + 64 + tx * 4) = c1;
    }
}

// ---------------------------------------------------------------------------
// Flash attention: per (b, h, 64-row q tile), stream 64-row K/V chunks.
// Online softmax with mask (mask==1 -> +(-1e9)). 4x4 per thread, 256 threads.
// ---------------------------------------------------------------------------
#define FLASH_SMEM ((4 * 64 * 65 + 3 * 64) * 4)

__global__ void __launch_bounds__(256) flash_kernel(const int* __restrict__ mask)
{
    extern __shared__ float sm[];
    float* sQ = sm;                 // [64][65]
    float* sK = sm + 64 * 65;       // [64][65]  sK[j][d]
    float* sV = sm + 2 * 64 * 65;   // [64][65]  sV[k][d]
    float* sP = sm + 3 * 64 * 65;   // [64][65]  scores / probs
    float* sM = sm + 4 * 64 * 65;   // [64] running max
    float* sL = sM + 64;            // [64] running denom
    float* sAl = sL + 64;           // [64] rescale factor

    const int tid = threadIdx.x;
    const int tx = tid & 15;
    const int ty = tid >> 4;
    const int qt = blockIdx.x;      // q tile (0..31)
    const int h  = blockIdx.y;      // head
    const int b  = blockIdx.z;      // batch

    const int qRow0 = b * SEQ + qt * 64;
    const int colBase = h * HDIM;

    // Vectorized Q fill: 64 rows x 16 float4 = 1024 float4, 4 per thread
    for (int idx = tid; idx < 64 * 16; idx += 256) {
        int r = idx >> 4, c4 = (idx & 15) * 4;
        float4 qv = *reinterpret_cast<const float4*>(
            g_q + (size_t)(qRow0 + r) * EDIM + colBase + c4);
        float* dst = sQ + r * 65 + c4;
        dst[0] = qv.x; dst[1] = qv.y; dst[2] = qv.z; dst[3] = qv.w;
    }
    if (tid < 64) { sM[tid] = -1e30f; sL[tid] = 0.f; }

    float acc[4][4];
    #pragma unroll
    for (int i = 0; i < 4; i++)
        #pragma unroll
        for (int j = 0; j < 4; j++) acc[i][j] = 0.f;
    __syncthreads();

    for (int kc = 0; kc < SEQ / 64; kc++) {
        const int kRow0 = b * SEQ + kc * 64;
        // Vectorized K+V fill
        for (int idx = tid; idx < 64 * 16; idx += 256) {
            int r = idx >> 4, c4 = (idx & 15) * 4;
            size_t off = (size_t)(kRow0 + r) * EDIM + colBase + c4;
            float4 kv = *reinterpret_cast<const float4*>(g_k + off);
            float4 vv = *reinterpret_cast<const float4*>(g_v + off);
            float* dk = sK + r * 65 + c4;
            float* dv = sV + r * 65 + c4;
            dk[0] = kv.x; dk[1] = kv.y; dk[2] = kv.z; dk[3] = kv.w;
            dv[0] = vv.x; dv[1] = vv.y; dv[2] = vv.z; dv[3] = vv.w;
        }
        __syncthreads();

        // S = (Q K^T) * 1/sqrt(D) + mask
        float s[4][4];
        #pragma unroll
        for (int i = 0; i < 4; i++)
            #pragma unroll
            for (int j = 0; j < 4; j++) s[i][j] = 0.f;

        #pragma unroll 8
        for (int d = 0; d < 64; d++) {
            float qa[4], kb[4];
            #pragma unroll
            for (int i = 0; i < 4; i++) qa[i] = sQ[(ty * 4 + i) * 65 + d];
            #pragma unroll
            for (int j = 0; j < 4; j++) kb[j] = sK[(tx * 4 + j) * 65 + d];
            #pragma unroll
            for (int i = 0; i < 4; i++)
                #pragma unroll
                for (int j = 0; j < 4; j++)
                    s[i][j] = fmaf(qa[i], kb[j], s[i][j]);
        }

        float mv[4];
        #pragma unroll
        for (int j = 0; j < 4; j++) {
            int m = mask[b * SEQ + kc * 64 + tx * 4 + j];
            mv[j] = m ? -1e9f : 0.f;
        }
        #pragma unroll
        for (int i = 0; i < 4; i++)
            #pragma unroll
            for (int j = 0; j < 4; j++)
                sP[(ty * 4 + i) * 65 + tx * 4 + j] = s[i][j] * 0.125f + mv[j];
        __syncthreads();

        // Online softmax row stats (one thread per row; banks conflict-free)
        if (tid < 64) {
            float* row = sP + tid * 65;
            float mo = sM[tid];
            float mx = mo;
            #pragma unroll 8
            for (int j = 0; j < 64; j++) mx = fmaxf(mx, row[j]);
            float sum = 0.f;
            #pragma unroll 8
            for (int j = 0; j < 64; j++) {
                float p = __expf(row[j] - mx);
                row[j] = p;
                sum += p;
            }
            float al = __expf(mo - mx);
            sL[tid] = sL[tid] * al + sum;
            sM[tid] = mx;
            sAl[tid] = al;
        }
        __syncthreads();

        // Rescale accumulator, then O += P @ V
        float al[4];
        #pragma unroll
        for (int i = 0; i < 4; i++) al[i] = sAl[ty * 4 + i];
        #pragma unroll
        for (int i = 0; i < 4; i++)
            #pragma unroll
            for (int j = 0; j < 4; j++) acc[i][j] *= al[i];

        #pragma unroll 8
        for (int kk = 0; kk < 64; kk++) {
            float pv[4], vv[4];
            #pragma unroll
            for (int i = 0; i < 4; i++) pv[i] = sP[(ty * 4 + i) * 65 + kk];
            #pragma unroll
            for (int j = 0; j < 4; j++) vv[j] = sV[kk * 65 + tx * 4 + j];
            #pragma unroll
            for (int i = 0; i < 4; i++)
                #pragma unroll
                for (int j = 0; j < 4; j++)
                    acc[i][j] = fmaf(pv[i], vv[j], acc[i][j]);
        }
        __syncthreads();
    }

    float li[4];
    #pragma unroll
    for (int i = 0; i < 4; i++) li[i] = 1.f / sL[ty * 4 + i];
    #pragma unroll
    for (int i = 0; i < 4; i++) {
        float4 o = make_float4(acc[i][0] * li[i], acc[i][1] * li[i],
                               acc[i][2] * li[i], acc[i][3] * li[i]);
        *reinterpret_cast<float4*>(
            g_ao + (size_t)(qRow0 + ty * 4 + i) * EDIM + colBase + tx * 4) = o;
    }
}

// ---------------------------------------------------------------------------
extern "C" void kernel_launch(void* const* d_in, const int* in_sizes, int n_in,
                              void* d_out, int out_size)
{
    (void)in_sizes; (void)n_in; (void)out_size;
    const float* value = (const float*)d_in[0];
    const float* key_  = (const float*)d_in[1];
    const float* query = (const float*)d_in[2];
    const int*   mask  = (const int*)d_in[3];
    const float* wq = (const float*)d_in[4];
    const float* bq = (const float*)d_in[5];
    const float* wk = (const float*)d_in[6];
    const float* bk = (const float*)d_in[7];
    const float* wv = (const float*)d_in[8];
    const float* bv = (const float*)d_in[9];
    const float* wo = (const float*)d_in[10];
    const float* bo = (const float*)d_in[11];
    float* out = (float*)d_out;

    float *q, *k, *v, *ao;
    cudaGetSymbolAddress((void**)&q, g_q);
    cudaGetSymbolAddress((void**)&k, g_k);
    cudaGetSymbolAddress((void**)&v, g_v);
    cudaGetSymbolAddress((void**)&ao, g_ao);

    cudaFuncSetAttribute(flash_kernel,
                         cudaFuncAttributeMaxDynamicSharedMemorySize, FLASH_SMEM);

    dim3 gGrid(EDIM / 128, NROWS / 128);   // (4, 128)
    gemm_bias_kernel<<<gGrid, 256>>>(query, wq, bq, q);
    gemm_bias_kernel<<<gGrid, 256>>>(key_,  wk, bk, k);
    gemm_bias_kernel<<<gGrid, 256>>>(value, wv, bv, v);

    flash_kernel<<<dim3(SEQ / 64, HEADS, BATCH), 256, FLASH_SMEM>>>(mask);

    gemm_bias_kernel<<<gGrid, 256>>>(ao, wo, bo, out);
}

// round 8
// speedup vs baseline: 5.3540x; 5.3540x over previous
#include <cuda_runtime.h>
#include <cuda_fp16.h>
#include <stdint.h>
#include <math.h>

#define NROWS (8 * 2048)
#define EDIM  512
#define HEADS 8
#define HDIM  64
#define SEQ   2048
#define BATCH 8
#define LOG2E 1.44269504f

// fp16 scratch (device globals: allocation-free per harness rules)
__device__ __align__(16) __half g_xh[NROWS * EDIM];   // converted activation input
__device__ __align__(16) __half g_qh[NROWS * EDIM];
__device__ __align__(16) __half g_kh[NROWS * EDIM];
__device__ __align__(16) __half g_vh[NROWS * EDIM];
__device__ __align__(16) __half g_aoh[NROWS * EDIM];
__device__ __align__(16) __half g_wt[4 * EDIM * EDIM]; // 4 weights, [n][k] fp16

// ---------------------------------------------------------------------------
// mma.sync m16n8k16 f16 -> f32
// ---------------------------------------------------------------------------
__device__ __forceinline__ void mma16816(float* c, const uint32_t* a,
                                         uint32_t b0, uint32_t b1)
{
    asm volatile(
        "mma.sync.aligned.m16n8k16.row.col.f32.f16.f16.f32 "
        "{%0,%1,%2,%3}, {%4,%5,%6,%7}, {%8,%9}, {%0,%1,%2,%3};"
        : "+f"(c[0]), "+f"(c[1]), "+f"(c[2]), "+f"(c[3])
        : "r"(a[0]), "r"(a[1]), "r"(a[2]), "r"(a[3]), "r"(b0), "r"(b1));
}

// ---------------------------------------------------------------------------
// Converters
// ---------------------------------------------------------------------------
__global__ void f32_to_f16_kernel(const float* __restrict__ in,
                                  __half* __restrict__ out, int n4)
{
    int i = blockIdx.x * blockDim.x + threadIdx.x;
    if (i < n4) {
        float4 v = reinterpret_cast<const float4*>(in)[i];
        __half2 a = __floats2half2_rn(v.x, v.y);
        __half2 b = __floats2half2_rn(v.z, v.w);
        reinterpret_cast<__half2*>(out)[2 * i]     = a;
        reinterpret_cast<__half2*>(out)[2 * i + 1] = b;
    }
}

// Wt[n][k] = W[k][n], fp32 -> fp16. 32x32 smem tile transpose, block (32,8).
__global__ void wt_convert_kernel(const float* __restrict__ W,
                                  __half* __restrict__ Wt)
{
    __shared__ float tile[32][33];
    int x = blockIdx.x * 32 + threadIdx.x;   // n (col of W)
    int y = blockIdx.y * 32 + threadIdx.y;   // k (row of W)
    #pragma unroll
    for (int i = 0; i < 32; i += 8)
        tile[threadIdx.y + i][threadIdx.x] = W[(size_t)(y + i) * EDIM + x];
    __syncthreads();
    int nk = blockIdx.y * 32 + threadIdx.x;  // k (contig in Wt row)
    int nn = blockIdx.x * 32 + threadIdx.y;  // n
    #pragma unroll
    for (int i = 0; i < 32; i += 8)
        Wt[(size_t)(nn + i) * EDIM + nk] =
            __float2half(tile[threadIdx.x][threadIdx.y + i]);
}

// ---------------------------------------------------------------------------
// HGEMM: C[16384,512] = A[16384,512] @ Wt^T + bias, HMMA m16n8k16.
// Block 128x128, k-step 32. 8 warps (4x2), warp tile 32x64.
// ---------------------------------------------------------------------------
template <bool HALF_OUT>
__global__ void __launch_bounds__(256, 2) hgemm_bias(
    const __half* __restrict__ A, const __half* __restrict__ Wt,
    const float* __restrict__ bias, void* __restrict__ Cout)
{
    __shared__ __align__(16) __half As[128][40];
    __shared__ __align__(16) __half Bs[128][40];

    const int tid  = threadIdx.x;
    const int lane = tid & 31, warp = tid >> 5;
    const int gid  = lane >> 2, tig = lane & 3;
    const int wm = warp >> 1, wn = warp & 1;
    const int rowBlock = blockIdx.y * 128, colBlock = blockIdx.x * 128;
    const int m0 = wm * 32, n0 = wn * 64;

    float c[2][8][4];
    #pragma unroll
    for (int mt = 0; mt < 2; mt++)
        #pragma unroll
        for (int nt = 0; nt < 8; nt++)
            #pragma unroll
            for (int i = 0; i < 4; i++) c[mt][nt][i] = 0.f;

    for (int k0 = 0; k0 < EDIM; k0 += 32) {
        #pragma unroll
        for (int i = 0; i < 2; i++) {
            int idx = tid + i * 256;          // 0..511
            int r = idx >> 2, seg = idx & 3;  // 4 x uint4 (8 halfs) per row
            *reinterpret_cast<uint4*>(&As[r][seg * 8]) =
                *reinterpret_cast<const uint4*>(
                    A + (size_t)(rowBlock + r) * EDIM + k0 + seg * 8);
            *reinterpret_cast<uint4*>(&Bs[r][seg * 8]) =
                *reinterpret_cast<const uint4*>(
                    Wt + (size_t)(colBlock + r) * EDIM + k0 + seg * 8);
        }
        __syncthreads();

        #pragma unroll
        for (int t = 0; t < 2; t++) {
            const int kk = t * 16;
            uint32_t af[2][4], bf[8][2];
            #pragma unroll
            for (int mt = 0; mt < 2; mt++) {
                const __half* ap = &As[m0 + mt * 16 + gid][kk + tig * 2];
                af[mt][0] = *reinterpret_cast<const uint32_t*>(ap);
                af[mt][1] = *reinterpret_cast<const uint32_t*>(ap + 8 * 40);
                af[mt][2] = *reinterpret_cast<const uint32_t*>(ap + 8);
                af[mt][3] = *reinterpret_cast<const uint32_t*>(ap + 8 * 40 + 8);
            }
            #pragma unroll
            for (int nt = 0; nt < 8; nt++) {
                const __half* bp = &Bs[n0 + nt * 8 + gid][kk + tig * 2];
                bf[nt][0] = *reinterpret_cast<const uint32_t*>(bp);
                bf[nt][1] = *reinterpret_cast<const uint32_t*>(bp + 8);
            }
            #pragma unroll
            for (int mt = 0; mt < 2; mt++)
                #pragma unroll
                for (int nt = 0; nt < 8; nt++)
                    mma16816(c[mt][nt], af[mt], bf[nt][0], bf[nt][1]);
        }
        __syncthreads();
    }

    #pragma unroll
    for (int mt = 0; mt < 2; mt++) {
        int r0 = rowBlock + m0 + mt * 16 + gid;
        #pragma unroll
        for (int nt = 0; nt < 8; nt++) {
            int col = colBlock + n0 + nt * 8 + tig * 2;
            float b0v = bias[col], b1v = bias[col + 1];
            if (HALF_OUT) {
                __half* o = (__half*)Cout;
                *reinterpret_cast<__half2*>(o + (size_t)r0 * EDIM + col) =
                    __floats2half2_rn(c[mt][nt][0] + b0v, c[mt][nt][1] + b1v);
                *reinterpret_cast<__half2*>(o + (size_t)(r0 + 8) * EDIM + col) =
                    __floats2half2_rn(c[mt][nt][2] + b0v, c[mt][nt][3] + b1v);
            } else {
                float* o = (float*)Cout;
                *reinterpret_cast<float2*>(o + (size_t)r0 * EDIM + col) =
                    make_float2(c[mt][nt][0] + b0v, c[mt][nt][1] + b1v);
                *reinterpret_cast<float2*>(o + (size_t)(r0 + 8) * EDIM + col) =
                    make_float2(c[mt][nt][2] + b0v, c[mt][nt][3] + b1v);
            }
        }
    }
}

// ---------------------------------------------------------------------------
// Flash attention, HMMA. Br=128, Bc=64. 8 warps; warp w owns rows w*16..+15.
// Softmax stats fully register-resident (lane-quad shuffles only).
// ---------------------------------------------------------------------------
__global__ void __launch_bounds__(256) flash_hmma(const int* __restrict__ mask)
{
    __shared__ __align__(16) __half sQ[128][72];
    __shared__ __align__(16) __half sK[64][72];
    __shared__ __align__(16) __half sVt[64][72];   // sVt[d][key]
    __shared__ float sMaskF[64];

    const int tid  = threadIdx.x;
    const int lane = tid & 31, warp = tid >> 5;
    const int gid  = lane >> 2, tig = lane & 3;
    const int qt = blockIdx.x, h = blockIdx.y, b = blockIdx.z;
    const int qRow0 = b * SEQ + qt * 128;
    const int colBase = h * HDIM;
    const int wr0 = warp * 16;

    // Q tile: 128 x 64 halfs = 1024 uint4
    #pragma unroll
    for (int i = 0; i < 4; i++) {
        int idx = tid + i * 256;
        int r = idx >> 3, seg = idx & 7;
        *reinterpret_cast<uint4*>(&sQ[r][seg * 8]) =
            *reinterpret_cast<const uint4*>(
                g_qh + (size_t)(qRow0 + r) * EDIM + colBase + seg * 8);
    }
    __syncthreads();

    uint32_t qf[4][4];
    #pragma unroll
    for (int t = 0; t < 4; t++) {
        const __half* qp = &sQ[wr0 + gid][t * 16 + tig * 2];
        qf[t][0] = *reinterpret_cast<const uint32_t*>(qp);
        qf[t][1] = *reinterpret_cast<const uint32_t*>(qp + 8 * 72);
        qf[t][2] = *reinterpret_cast<const uint32_t*>(qp + 8);
        qf[t][3] = *reinterpret_cast<const uint32_t*>(qp + 8 * 72 + 8);
    }

    float of[8][4];
    #pragma unroll
    for (int nt = 0; nt < 8; nt++)
        #pragma unroll
        for (int i = 0; i < 4; i++) of[nt][i] = 0.f;
    float m_lo = -1e30f, m_hi = -1e30f, l_lo = 0.f, l_hi = 0.f;

    for (int kc = 0; kc < SEQ / 64; kc++) {
        const int kRow0 = b * SEQ + kc * 64;

        // K tile: 64 x 64 halfs = 512 uint4
        #pragma unroll
        for (int i = 0; i < 2; i++) {
            int idx = tid + i * 256;
            int r = idx >> 3, seg = idx & 7;
            *reinterpret_cast<uint4*>(&sK[r][seg * 8]) =
                *reinterpret_cast<const uint4*>(
                    g_kh + (size_t)(kRow0 + r) * EDIM + colBase + seg * 8);
        }
        // V transpose into sVt[d][key] via 2x2 half2 staging
        #pragma unroll
        for (int i = 0; i < 4; i++) {
            int e = tid + i * 256;          // 0..1023: (keypair, dpair)
            int r2 = e >> 5, c2 = e & 31;
            const __half* vp = g_vh + (size_t)(kRow0 + 2 * r2) * EDIM + colBase + 2 * c2;
            __half2 va = *reinterpret_cast<const __half2*>(vp);
            __half2 vb = *reinterpret_cast<const __half2*>(vp + EDIM);
            *reinterpret_cast<__half2*>(&sVt[2 * c2][2 * r2]) =
                __halves2half2(__low2half(va), __low2half(vb));
            *reinterpret_cast<__half2*>(&sVt[2 * c2 + 1][2 * r2]) =
                __halves2half2(__high2half(va), __high2half(vb));
        }
        if (tid < 64) {
            int mi = mask[b * SEQ + kc * 64 + tid];
            sMaskF[tid] = mi ? (-1.0e9f * LOG2E) : 0.f;
        }
        __syncthreads();

        // S = Q K^T (fp32 frags)
        float sf[8][4];
        #pragma unroll
        for (int nt = 0; nt < 8; nt++)
            #pragma unroll
            for (int i = 0; i < 4; i++) sf[nt][i] = 0.f;
        #pragma unroll
        for (int t = 0; t < 4; t++)
            #pragma unroll
            for (int nt = 0; nt < 8; nt++) {
                const __half* bp = &sK[nt * 8 + gid][t * 16 + tig * 2];
                uint32_t b0 = *reinterpret_cast<const uint32_t*>(bp);
                uint32_t b1 = *reinterpret_cast<const uint32_t*>(bp + 8);
                mma16816(sf[nt], qf[t], b0, b1);
            }

        // scale into log2 domain + mask, then online softmax
        const float sc = 0.125f * LOG2E;
        float mx_lo = -1e30f, mx_hi = -1e30f;
        #pragma unroll
        for (int nt = 0; nt < 8; nt++) {
            float p0 = sMaskF[nt * 8 + tig * 2];
            float p1 = sMaskF[nt * 8 + tig * 2 + 1];
            sf[nt][0] = fmaf(sf[nt][0], sc, p0);
            sf[nt][1] = fmaf(sf[nt][1], sc, p1);
            sf[nt][2] = fmaf(sf[nt][2], sc, p0);
            sf[nt][3] = fmaf(sf[nt][3], sc, p1);
            mx_lo = fmaxf(mx_lo, fmaxf(sf[nt][0], sf[nt][1]));
            mx_hi = fmaxf(mx_hi, fmaxf(sf[nt][2], sf[nt][3]));
        }
        mx_lo = fmaxf(mx_lo, __shfl_xor_sync(0xffffffffu, mx_lo, 1));
        mx_lo = fmaxf(mx_lo, __shfl_xor_sync(0xffffffffu, mx_lo, 2));
        mx_hi = fmaxf(mx_hi, __shfl_xor_sync(0xffffffffu, mx_hi, 1));
        mx_hi = fmaxf(mx_hi, __shfl_xor_sync(0xffffffffu, mx_hi, 2));
        float mn_lo = fmaxf(m_lo, mx_lo), mn_hi = fmaxf(m_hi, mx_hi);
        float al_lo = exp2f(m_lo - mn_lo), al_hi = exp2f(m_hi - mn_hi);

        float sum_lo = 0.f, sum_hi = 0.f;
        uint32_t pf[4][4];
        #pragma unroll
        for (int nt = 0; nt < 8; nt++) {
            float p0 = exp2f(sf[nt][0] - mn_lo);
            float p1 = exp2f(sf[nt][1] - mn_lo);
            float p2 = exp2f(sf[nt][2] - mn_hi);
            float p3 = exp2f(sf[nt][3] - mn_hi);
            sum_lo += p0 + p1; sum_hi += p2 + p3;
            int t = nt >> 1;
            __half2 lo2 = __floats2half2_rn(p0, p1);
            __half2 hi2 = __floats2half2_rn(p2, p3);
            if ((nt & 1) == 0) {
                pf[t][0] = *reinterpret_cast<uint32_t*>(&lo2);
                pf[t][1] = *reinterpret_cast<uint32_t*>(&hi2);
            } else {
                pf[t][2] = *reinterpret_cast<uint32_t*>(&lo2);
                pf[t][3] = *reinterpret_cast<uint32_t*>(&hi2);
            }
        }
        sum_lo += __shfl_xor_sync(0xffffffffu, sum_lo, 1);
        sum_lo += __shfl_xor_sync(0xffffffffu, sum_lo, 2);
        sum_hi += __shfl_xor_sync(0xffffffffu, sum_hi, 1);
        sum_hi += __shfl_xor_sync(0xffffffffu, sum_hi, 2);
        l_lo = l_lo * al_lo + sum_lo;  m_lo = mn_lo;
        l_hi = l_hi * al_hi + sum_hi;  m_hi = mn_hi;

        #pragma unroll
        for (int nt = 0; nt < 8; nt++) {
            of[nt][0] *= al_lo; of[nt][1] *= al_lo;
            of[nt][2] *= al_hi; of[nt][3] *= al_hi;
        }

        // O += P @ V   (B = sVt[d][key], n = d, k = key)
        #pragma unroll
        for (int t = 0; t < 4; t++)
            #pragma unroll
            for (int nt = 0; nt < 8; nt++) {
                const __half* bp = &sVt[nt * 8 + gid][t * 16 + tig * 2];
                uint32_t b0 = *reinterpret_cast<const uint32_t*>(bp);
                uint32_t b1 = *reinterpret_cast<const uint32_t*>(bp + 8);
                mma16816(of[nt], pf[t], b0, b1);
            }
        __syncthreads();
    }

    float r_lo = 1.f / l_lo, r_hi = 1.f / l_hi;
    #pragma unroll
    for (int nt = 0; nt < 8; nt++) {
        int col = colBase + nt * 8 + tig * 2;
        *reinterpret_cast<__half2*>(
            g_aoh + (size_t)(qRow0 + wr0 + gid) * EDIM + col) =
            __floats2half2_rn(of[nt][0] * r_lo, of[nt][1] * r_lo);
        *reinterpret_cast<__half2*>(
            g_aoh + (size_t)(qRow0 + wr0 + gid + 8) * EDIM + col) =
            __floats2half2_rn(of[nt][2] * r_hi, of[nt][3] * r_hi);
    }
}

// ---------------------------------------------------------------------------
extern "C" void kernel_launch(void* const* d_in, const int* in_sizes, int n_in,
                              void* d_out, int out_size)
{
    (void)in_sizes; (void)n_in; (void)out_size;
    const float* value = (const float*)d_in[0];
    const float* key_  = (const float*)d_in[1];
    const float* query = (const float*)d_in[2];
    const int*   mask  = (const int*)d_in[3];
    const float* wq = (const float*)d_in[4];
    const float* bq = (const float*)d_in[5];
    const float* wk = (const float*)d_in[6];
    const float* bk = (const float*)d_in[7];
    const float* wv = (const float*)d_in[8];
    const float* bv = (const float*)d_in[9];
    const float* wo = (const float*)d_in[10];
    const float* bo = (const float*)d_in[11];
    float* out = (float*)d_out;

    __half *xh, *qh, *kh, *vh, *aoh, *wt;
    cudaGetSymbolAddress((void**)&xh,  g_xh);
    cudaGetSymbolAddress((void**)&qh,  g_qh);
    cudaGetSymbolAddress((void**)&kh,  g_kh);
    cudaGetSymbolAddress((void**)&vh,  g_vh);
    cudaGetSymbolAddress((void**)&aoh, g_aoh);
    cudaGetSymbolAddress((void**)&wt,  g_wt);
    __half* wt0 = wt;
    __half* wt1 = wt + EDIM * EDIM;
    __half* wt2 = wt + 2 * EDIM * EDIM;
    __half* wt3 = wt + 3 * EDIM * EDIM;

    dim3 tGrid(16, 16), tBlk(32, 8);
    wt_convert_kernel<<<tGrid, tBlk>>>(wq, wt0);
    wt_convert_kernel<<<tGrid, tBlk>>>(wk, wt1);
    wt_convert_kernel<<<tGrid, tBlk>>>(wv, wt2);
    wt_convert_kernel<<<tGrid, tBlk>>>(wo, wt3);

    const int n4 = NROWS * EDIM / 4;
    const int cBlocks = (n4 + 255) / 256;
    dim3 gGrid(EDIM / 128, NROWS / 128);   // (4, 128)

    f32_to_f16_kernel<<<cBlocks, 256>>>(query, xh, n4);
    hgemm_bias<true><<<gGrid, 256>>>(xh, wt0, bq, qh);
    f32_to_f16_kernel<<<cBlocks, 256>>>(key_, xh, n4);
    hgemm_bias<true><<<gGrid, 256>>>(xh, wt1, bk, kh);
    f32_to_f16_kernel<<<cBlocks, 256>>>(value, xh, n4);
    hgemm_bias<true><<<gGrid, 256>>>(xh, wt2, bv, vh);

    flash_hmma<<<dim3(SEQ / 128, HEADS, BATCH), 256>>>(mask);

    hgemm_bias<false><<<gGrid, 256>>>(aoh, wt3, bo, out);
}

// round 10
// speedup vs baseline: 5.9370x; 1.1089x over previous
#include <cuda_runtime.h>
#include <cuda_fp16.h>
#include <stdint.h>
#include <math.h>

#define NROWS (8 * 2048)
#define EDIM  512
#define HEADS 8
#define HDIM  64
#define SEQ   2048
#define BATCH 8
#define LOG2E 1.44269504f

// fp16 scratch (device globals: allocation-free per harness rules)
__device__ __align__(16) __half g_qh[NROWS * EDIM];
__device__ __align__(16) __half g_kh[NROWS * EDIM];
__device__ __align__(16) __half g_vh[NROWS * EDIM];
__device__ __align__(16) __half g_aoh[NROWS * EDIM];
__device__ __align__(16) __half g_wt[4 * EDIM * EDIM]; // 4 weights, [n][k] fp16

// ---------------------------------------------------------------------------
// PTX helpers
// ---------------------------------------------------------------------------
__device__ __forceinline__ uint32_t sptr(const void* p) {
    return (uint32_t)__cvta_generic_to_shared(p);
}

__device__ __forceinline__ void mma16816(float* c, const uint32_t* a,
                                         uint32_t b0, uint32_t b1)
{
    asm volatile(
        "mma.sync.aligned.m16n8k16.row.col.f32.f16.f16.f32 "
        "{%0,%1,%2,%3}, {%4,%5,%6,%7}, {%8,%9}, {%0,%1,%2,%3};"
        : "+f"(c[0]), "+f"(c[1]), "+f"(c[2]), "+f"(c[3])
        : "r"(a[0]), "r"(a[1]), "r"(a[2]), "r"(a[3]), "r"(b0), "r"(b1));
}

__device__ __forceinline__ void ldsm4(uint32_t& r0, uint32_t& r1,
                                      uint32_t& r2, uint32_t& r3, uint32_t a)
{
    asm volatile("ldmatrix.sync.aligned.m8n8.x4.shared.b16 {%0,%1,%2,%3}, [%4];"
                 : "=r"(r0), "=r"(r1), "=r"(r2), "=r"(r3) : "r"(a));
}

// ---------------------------------------------------------------------------
// Weight transpose+convert: Wt[n][k] = W[k][n], fp32 -> fp16.
// ---------------------------------------------------------------------------
__global__ void wt_convert_kernel(const float* __restrict__ W,
                                  __half* __restrict__ Wt)
{
    __shared__ float tile[32][33];
    int x = blockIdx.x * 32 + threadIdx.x;
    int y = blockIdx.y * 32 + threadIdx.y;
    #pragma unroll
    for (int i = 0; i < 32; i += 8)
        tile[threadIdx.y + i][threadIdx.x] = W[(size_t)(y + i) * EDIM + x];
    __syncthreads();
    int nk = blockIdx.y * 32 + threadIdx.x;
    int nn = blockIdx.x * 32 + threadIdx.y;
    #pragma unroll
    for (int i = 0; i < 32; i += 8)
        Wt[(size_t)(nn + i) * EDIM + nk] =
            __float2half(tile[threadIdx.x][threadIdx.y + i]);
}

// ---------------------------------------------------------------------------
// HGEMM: C[16384,512] = A @ Wt^T + bias. Block 128x128, k-step 32, 8 warps.
// blockIdx.z selects {A, bias, out, weight-slice} (QKV batched in one launch).
// A is fp32 (converted during staging) when AF32, else fp16.
// Double-buffered smem + register-prefetched GMEM loads + ldmatrix fragments.
// ---------------------------------------------------------------------------
template <bool AF32, bool HALF_OUT>
__global__ void __launch_bounds__(256, 2) hgemm_bias(
    const void* __restrict__ A0, const void* __restrict__ A1,
    const void* __restrict__ A2, const __half* __restrict__ WtBase,
    const float* __restrict__ bias0, const float* __restrict__ bias1,
    const float* __restrict__ bias2,
    void* __restrict__ O0, void* __restrict__ O1, void* __restrict__ O2)
{
    __shared__ __align__(16) __half As[2][128][40];
    __shared__ __align__(16) __half Bs[2][128][40];

    const int z = blockIdx.z;
    const void*  A    = (z == 0) ? A0 : (z == 1) ? A1 : A2;
    const float* bias = (z == 0) ? bias0 : (z == 1) ? bias1 : bias2;
    void*        Cout = (z == 0) ? O0 : (z == 1) ? O1 : O2;
    const __half* Wt  = WtBase + (size_t)z * EDIM * EDIM;

    const int tid  = threadIdx.x;
    const int lane = tid & 31, warp = tid >> 5;
    const int gid  = lane >> 2, tig = lane & 3;
    const int g8   = lane >> 3, i8 = lane & 7;
    const int wm = warp >> 1, wn = warp & 1;
    const int rowBlock = blockIdx.y * 128, colBlock = blockIdx.x * 128;
    const int m0 = wm * 32, n0 = wn * 64;

    float c[2][8][4];
    #pragma unroll
    for (int mt = 0; mt < 2; mt++)
        #pragma unroll
        for (int nt = 0; nt < 8; nt++)
            #pragma unroll
            for (int i = 0; i < 4; i++) c[mt][nt][i] = 0.f;

    float4 aF[4];
    uint4  aH[2];
    uint4  bR[2];

#define LDG_TILE(kt) do {                                                     \
    int k0_ = (kt) * 32;                                                      \
    if (AF32) {                                                               \
        const float* Af_ = (const float*)A;                                   \
        for (int j = 0; j < 4; j++) {                                         \
            int task = tid + j * 256, r = task >> 3, cc = (task & 7) * 4;     \
            aF[j] = *(const float4*)(Af_ + (size_t)(rowBlock + r) * EDIM + k0_ + cc); \
        }                                                                     \
    } else {                                                                  \
        const __half* Ah_ = (const __half*)A;                                 \
        for (int j = 0; j < 2; j++) {                                         \
            int task = tid + j * 256, r = task >> 2, cc = (task & 3) * 8;     \
            aH[j] = *(const uint4*)(Ah_ + (size_t)(rowBlock + r) * EDIM + k0_ + cc); \
        }                                                                     \
    }                                                                         \
    for (int j = 0; j < 2; j++) {                                             \
        int task = tid + j * 256, r = task >> 2, cc = (task & 3) * 8;         \
        bR[j] = *(const uint4*)(Wt + (size_t)(colBlock + r) * EDIM + k0_ + cc); \
    }                                                                         \
} while (0)

#define STS_TILE(bf_) do {                                                    \
    if (AF32) {                                                               \
        for (int j = 0; j < 4; j++) {                                         \
            int task = tid + j * 256, r = task >> 3, cc = (task & 7) * 4;     \
            __half2 h0_ = __floats2half2_rn(aF[j].x, aF[j].y);                \
            __half2 h1_ = __floats2half2_rn(aF[j].z, aF[j].w);                \
            uint2 u_; u_.x = *(uint32_t*)&h0_; u_.y = *(uint32_t*)&h1_;       \
            *(uint2*)&As[bf_][r][cc] = u_;                                    \
        }                                                                     \
    } else {                                                                  \
        for (int j = 0; j < 2; j++) {                                         \
            int task = tid + j * 256, r = task >> 2, cc = (task & 3) * 8;     \
            *(uint4*)&As[bf_][r][cc] = aH[j];                                 \
        }                                                                     \
    }                                                                         \
    for (int j = 0; j < 2; j++) {                                             \
        int task = tid + j * 256, r = task >> 2, cc = (task & 3) * 8;         \
        *(uint4*)&Bs[bf_][r][cc] = bR[j];                                     \
    }                                                                         \
} while (0)

    LDG_TILE(0);
    STS_TILE(0);
    __syncthreads();

    for (int it = 0; it < 16; it++) {
        const int buf = it & 1;
        if (it < 15) LDG_TILE(it + 1);

        #pragma unroll
        for (int t = 0; t < 2; t++) {
            const int kk = t * 16;
            uint32_t af[2][4], bf[4][4];
            #pragma unroll
            for (int mt = 0; mt < 2; mt++)
                ldsm4(af[mt][0], af[mt][1], af[mt][2], af[mt][3],
                      sptr(&As[buf][m0 + mt * 16 + i8 + 8 * (g8 & 1)]
                              [kk + 8 * (g8 >> 1)]));
            #pragma unroll
            for (int np = 0; np < 4; np++)
                ldsm4(bf[np][0], bf[np][1], bf[np][2], bf[np][3],
                      sptr(&Bs[buf][n0 + np * 16 + i8 + 8 * (g8 >> 1)]
                              [kk + 8 * (g8 & 1)]));
            #pragma unroll
            for (int mt = 0; mt < 2; mt++)
                #pragma unroll
                for (int np = 0; np < 4; np++) {
                    mma16816(c[mt][2 * np],     af[mt], bf[np][0], bf[np][1]);
                    mma16816(c[mt][2 * np + 1], af[mt], bf[np][2], bf[np][3]);
                }
        }

        if (it < 15) STS_TILE(buf ^ 1);
        __syncthreads();
    }

    #pragma unroll
    for (int mt = 0; mt < 2; mt++) {
        int r0 = rowBlock + m0 + mt * 16 + gid;
        #pragma unroll
        for (int nt = 0; nt < 8; nt++) {
            int col = colBlock + n0 + nt * 8 + tig * 2;
            float b0v = bias[col], b1v = bias[col + 1];
            if (HALF_OUT) {
                __half* o = (__half*)Cout;
                *reinterpret_cast<__half2*>(o + (size_t)r0 * EDIM + col) =
                    __floats2half2_rn(c[mt][nt][0] + b0v, c[mt][nt][1] + b1v);
                *reinterpret_cast<__half2*>(o + (size_t)(r0 + 8) * EDIM + col) =
                    __floats2half2_rn(c[mt][nt][2] + b0v, c[mt][nt][3] + b1v);
            } else {
                float* o = (float*)Cout;
                *reinterpret_cast<float2*>(o + (size_t)r0 * EDIM + col) =
                    make_float2(c[mt][nt][0] + b0v, c[mt][nt][1] + b1v);
                *reinterpret_cast<float2*>(o + (size_t)(r0 + 8) * EDIM + col) =
                    make_float2(c[mt][nt][2] + b0v, c[mt][nt][3] + b1v);
            }
        }
    }
#undef LDG_TILE
#undef STS_TILE
}

// ---------------------------------------------------------------------------
// Flash attention, HMMA — round-8 verbatim (known good).
// Br=128, Bc=64, 8 warps; warp w owns rows w*16..+15. Manual fragment loads,
// explicit V-transpose staging, register-resident softmax stats.
// ---------------------------------------------------------------------------
__global__ void __launch_bounds__(256) flash_hmma(const int* __restrict__ mask)
{
    __shared__ __align__(16) __half sQ[128][72];
    __shared__ __align__(16) __half sK[64][72];
    __shared__ __align__(16) __half sVt[64][72];   // sVt[d][key]
    __shared__ float sMaskF[64];

    const int tid  = threadIdx.x;
    const int lane = tid & 31, warp = tid >> 5;
    const int gid  = lane >> 2, tig = lane & 3;
    const int qt = blockIdx.x, h = blockIdx.y, b = blockIdx.z;
    const int qRow0 = b * SEQ + qt * 128;
    const int colBase = h * HDIM;
    const int wr0 = warp * 16;

    // Q tile: 128 x 64 halfs = 1024 uint4
    #pragma unroll
    for (int i = 0; i < 4; i++) {
        int idx = tid + i * 256;
        int r = idx >> 3, seg = idx & 7;
        *reinterpret_cast<uint4*>(&sQ[r][seg * 8]) =
            *reinterpret_cast<const uint4*>(
                g_qh + (size_t)(qRow0 + r) * EDIM + colBase + seg * 8);
    }
    __syncthreads();

    uint32_t qf[4][4];
    #pragma unroll
    for (int t = 0; t < 4; t++) {
        const __half* qp = &sQ[wr0 + gid][t * 16 + tig * 2];
        qf[t][0] = *reinterpret_cast<const uint32_t*>(qp);
        qf[t][1] = *reinterpret_cast<const uint32_t*>(qp + 8 * 72);
        qf[t][2] = *reinterpret_cast<const uint32_t*>(qp + 8);
        qf[t][3] = *reinterpret_cast<const uint32_t*>(qp + 8 * 72 + 8);
    }

    float of[8][4];
    #pragma unroll
    for (int nt = 0; nt < 8; nt++)
        #pragma unroll
        for (int i = 0; i < 4; i++) of[nt][i] = 0.f;
    float m_lo = -1e30f, m_hi = -1e30f, l_lo = 0.f, l_hi = 0.f;

    for (int kc = 0; kc < SEQ / 64; kc++) {
        const int kRow0 = b * SEQ + kc * 64;

        // K tile: 64 x 64 halfs = 512 uint4
        #pragma unroll
        for (int i = 0; i < 2; i++) {
            int idx = tid + i * 256;
            int r = idx >> 3, seg = idx & 7;
            *reinterpret_cast<uint4*>(&sK[r][seg * 8]) =
                *reinterpret_cast<const uint4*>(
                    g_kh + (size_t)(kRow0 + r) * EDIM + colBase + seg * 8);
        }
        // V transpose into sVt[d][key] via 2x2 half2 staging
        #pragma unroll
        for (int i = 0; i < 4; i++) {
            int e = tid + i * 256;          // 0..1023: (keypair, dpair)
            int r2 = e >> 5, c2 = e & 31;
            const __half* vp = g_vh + (size_t)(kRow0 + 2 * r2) * EDIM + colBase + 2 * c2;
            __half2 va = *reinterpret_cast<const __half2*>(vp);
            __half2 vb = *reinterpret_cast<const __half2*>(vp + EDIM);
            *reinterpret_cast<__half2*>(&sVt[2 * c2][2 * r2]) =
                __halves2half2(__low2half(va), __low2half(vb));
            *reinterpret_cast<__half2*>(&sVt[2 * c2 + 1][2 * r2]) =
                __halves2half2(__high2half(va), __high2half(vb));
        }
        if (tid < 64) {
            int mi = mask[b * SEQ + kc * 64 + tid];
            sMaskF[tid] = mi ? (-1.0e9f * LOG2E) : 0.f;
        }
        __syncthreads();

        // S = Q K^T (fp32 frags)
        float sf[8][4];
        #pragma unroll
        for (int nt = 0; nt < 8; nt++)
            #pragma unroll
            for (int i = 0; i < 4; i++) sf[nt][i] = 0.f;
        #pragma unroll
        for (int t = 0; t < 4; t++)
            #pragma unroll
            for (int nt = 0; nt < 8; nt++) {
                const __half* bp = &sK[nt * 8 + gid][t * 16 + tig * 2];
                uint32_t b0 = *reinterpret_cast<const uint32_t*>(bp);
                uint32_t b1 = *reinterpret_cast<const uint32_t*>(bp + 8);
                mma16816(sf[nt], qf[t], b0, b1);
            }

        // scale into log2 domain + mask, then online softmax
        const float sc = 0.125f * LOG2E;
        float mx_lo = -1e30f, mx_hi = -1e30f;
        #pragma unroll
        for (int nt = 0; nt < 8; nt++) {
            float p0 = sMaskF[nt * 8 + tig * 2];
            float p1 = sMaskF[nt * 8 + tig * 2 + 1];
            sf[nt][0] = fmaf(sf[nt][0], sc, p0);
            sf[nt][1] = fmaf(sf[nt][1], sc, p1);
            sf[nt][2] = fmaf(sf[nt][2], sc, p0);
            sf[nt][3] = fmaf(sf[nt][3], sc, p1);
            mx_lo = fmaxf(mx_lo, fmaxf(sf[nt][0], sf[nt][1]));
            mx_hi = fmaxf(mx_hi, fmaxf(sf[nt][2], sf[nt][3]));
        }
        mx_lo = fmaxf(mx_lo, __shfl_xor_sync(0xffffffffu, mx_lo, 1));
        mx_lo = fmaxf(mx_lo, __shfl_xor_sync(0xffffffffu, mx_lo, 2));
        mx_hi = fmaxf(mx_hi, __shfl_xor_sync(0xffffffffu, mx_hi, 1));
        mx_hi = fmaxf(mx_hi, __shfl_xor_sync(0xffffffffu, mx_hi, 2));
        float mn_lo = fmaxf(m_lo, mx_lo), mn_hi = fmaxf(m_hi, mx_hi);
        float al_lo = exp2f(m_lo - mn_lo), al_hi = exp2f(m_hi - mn_hi);

        float sum_lo = 0.f, sum_hi = 0.f;
        uint32_t pf[4][4];
        #pragma unroll
        for (int nt = 0; nt < 8; nt++) {
            float p0 = exp2f(sf[nt][0] - mn_lo);
            float p1 = exp2f(sf[nt][1] - mn_lo);
            float p2 = exp2f(sf[nt][2] - mn_hi);
            float p3 = exp2f(sf[nt][3] - mn_hi);
            sum_lo += p0 + p1; sum_hi += p2 + p3;
            int t = nt >> 1;
            __half2 lo2 = __floats2half2_rn(p0, p1);
            __half2 hi2 = __floats2half2_rn(p2, p3);
            if ((nt & 1) == 0) {
                pf[t][0] = *reinterpret_cast<uint32_t*>(&lo2);
                pf[t][1] = *reinterpret_cast<uint32_t*>(&hi2);
            } else {
                pf[t][2] = *reinterpret_cast<uint32_t*>(&lo2);
                pf[t][3] = *reinterpret_cast<uint32_t*>(&hi2);
            }
        }
        sum_lo += __shfl_xor_sync(0xffffffffu, sum_lo, 1);
        sum_lo += __shfl_xor_sync(0xffffffffu, sum_lo, 2);
        sum_hi += __shfl_xor_sync(0xffffffffu, sum_hi, 1);
        sum_hi += __shfl_xor_sync(0xffffffffu, sum_hi, 2);
        l_lo = l_lo * al_lo + sum_lo;  m_lo = mn_lo;
        l_hi = l_hi * al_hi + sum_hi;  m_hi = mn_hi;

        #pragma unroll
        for (int nt = 0; nt < 8; nt++) {
            of[nt][0] *= al_lo; of[nt][1] *= al_lo;
            of[nt][2] *= al_hi; of[nt][3] *= al_hi;
        }

        // O += P @ V   (B = sVt[d][key], n = d, k = key)
        #pragma unroll
        for (int t = 0; t < 4; t++)
            #pragma unroll
            for (int nt = 0; nt < 8; nt++) {
                const __half* bp = &sVt[nt * 8 + gid][t * 16 + tig * 2];
                uint32_t b0 = *reinterpret_cast<const uint32_t*>(bp);
                uint32_t b1 = *reinterpret_cast<const uint32_t*>(bp + 8);
                mma16816(of[nt], pf[t], b0, b1);
            }
        __syncthreads();
    }

    float r_lo = 1.f / l_lo, r_hi = 1.f / l_hi;
    #pragma unroll
    for (int nt = 0; nt < 8; nt++) {
        int col = colBase + nt * 8 + tig * 2;
        *reinterpret_cast<__half2*>(
            g_aoh + (size_t)(qRow0 + wr0 + gid) * EDIM + col) =
            __floats2half2_rn(of[nt][0] * r_lo, of[nt][1] * r_lo);
        *reinterpret_cast<__half2*>(
            g_aoh + (size_t)(qRow0 + wr0 + gid + 8) * EDIM + col) =
            __floats2half2_rn(of[nt][2] * r_hi, of[nt][3] * r_hi);
    }
}

// ---------------------------------------------------------------------------
extern "C" void kernel_launch(void* const* d_in, const int* in_sizes, int n_in,
                              void* d_out, int out_size)
{
    (void)in_sizes; (void)n_in; (void)out_size;
    const float* value = (const float*)d_in[0];
    const float* key_  = (const float*)d_in[1];
    const float* query = (const float*)d_in[2];
    const int*   mask  = (const int*)d_in[3];
    const float* wq = (const float*)d_in[4];
    const float* bq = (const float*)d_in[5];
    const float* wk = (const float*)d_in[6];
    const float* bk = (const float*)d_in[7];
    const float* wv = (const float*)d_in[8];
    const float* bv = (const float*)d_in[9];
    const float* wo = (const float*)d_in[10];
    const float* bo = (const float*)d_in[11];
    float* out = (float*)d_out;

    __half *qh, *kh, *vh, *aoh, *wt;
    cudaGetSymbolAddress((void**)&qh,  g_qh);
    cudaGetSymbolAddress((void**)&kh,  g_kh);
    cudaGetSymbolAddress((void**)&vh,  g_vh);
    cudaGetSymbolAddress((void**)&aoh, g_aoh);
    cudaGetSymbolAddress((void**)&wt,  g_wt);
    __half* wt3 = wt + 3 * (size_t)EDIM * EDIM;

    dim3 tGrid(16, 16), tBlk(32, 8);
    wt_convert_kernel<<<tGrid, tBlk>>>(wq, wt);
    wt_convert_kernel<<<tGrid, tBlk>>>(wk, wt + (size_t)EDIM * EDIM);
    wt_convert_kernel<<<tGrid, tBlk>>>(wv, wt + 2 * (size_t)EDIM * EDIM);
    wt_convert_kernel<<<tGrid, tBlk>>>(wo, wt3);

    // Q, K, V projections batched in one launch (fp32 in, fp16 out)
    hgemm_bias<true, true><<<dim3(EDIM / 128, NROWS / 128, 3), 256>>>(
        query, key_, value, wt, bq, bk, bv, qh, kh, vh);

    flash_hmma<<<dim3(SEQ / 128, HEADS, BATCH), 256>>>(mask);

    // Output projection (fp16 in, fp32 out)
    hgemm_bias<false, false><<<dim3(EDIM / 128, NROWS / 128, 1), 256>>>(
        aoh, aoh, aoh, wt3, bo, bo, bo, out, out, out);
}